// round 15
// baseline (speedup 1.0000x reference)
#include <cuda_runtime.h>
#include <math.h>

#define NPIX   262144
#define NCH    256
#define NK     24            // n_knots + degree + 1
#define ND     22            // second-difference rows
#define PPI    32            // pixels per tile
#define PF     4             // s_obs ring depth (power of 2, <= PPI)
#define NTILES (NPIX / PPI)  // 8192
#define GRID   740           // 148 SMs * 5 resident blocks

#define C1F    1.191042e-08f
#define C2L2EF (1.4387769f * 1.4426950408889634f)   // C2 * log2(e)

// ---------------- persistent device scratch (no allocations) ----------------
__device__ double   g_res;
__device__ double   g_ss;
__device__ double   g_bv;
__device__ unsigned g_count;
__device__ unsigned g_next = GRID;    // dynamic tile cursor (reset each launch)

__global__ void __launch_bounds__(256, 5)
fused_kernel(const float* __restrict__ s_obs,
             const float* __restrict__ temperature,
             const float* __restrict__ beta,
             const float* __restrict__ view_factor,
             const float* __restrict__ s_sky,
             const float* __restrict__ s_ground,
             const float* __restrict__ phi,
             const float* __restrict__ wn,
             float* __restrict__ s_model,     // 4B aligned only (d_out+1)
             float* __restrict__ out_total,
             int write_total)
{
    // 4 shifted copies of the beta tile: copy s holds beta[k+s] at index k,
    // so window beta[k0..k0+3] is one aligned LDS.128 from copy (k0&3).
    __shared__ float    sbc[2][4][PPI * NK];   // 2 x 4 x 768 floats = 24.6 KB
    __shared__ float2   sTV[2][PPI];           // (1/T, vf) per pixel
    __shared__ float    wred[3][8];
    __shared__ unsigned sNext[2];              // parity-buffered next-tile id

    const int t    = threadIdx.x;        // t == channel
    const int wid  = t >> 5;
    const int lane = t & 31;

    // ---- per-channel constants (one-time; phi/wn tiny, L2-resident) ----
    const float* row = phi + t * NK;
    int k0 = 0;
    #pragma unroll
    for (int k = 0; k < NK; ++k) {
        if (row[k] != 0.0f) { k0 = k; break; }
    }
    if (k0 > NK - 4) k0 = NK - 4;
    const float w0 = row[k0],     w1 = row[k0 + 1];
    const float w2 = row[k0 + 2], w3 = row[k0 + 3];
    const float v   = wn[t];
    const float c1  = C1F * v * v * v;
    const float c2l = C2L2EF * v;        // exp(C2 v/T) == exp2(c2l/T)
    const float sg  = s_ground[t];
    const float dsg = s_sky[t] - sg;

    const int csel = k0 & 3;             // which shifted copy
    const int coff = k0 - csel;          // 16B-aligned float offset in that copy

    // smoothness: PPI*ND = 704 rows; thread handles t, t+256, t+512 (if <704)
    const int  ia = t,        oa   = (ia / ND) * NK + (ia % ND);
    const int  ib = t + 256,  obs_ = (ib / ND) * NK + (ib % ND);
    const int  ic = t + 512,  oc   = (ic / ND) * NK + (ic % ND);
    const bool has_c = ic < PPI * ND;    // t < 192

    float rs = 0.0f, bvs = 0.0f, sss = 0.0f;

    // stage beta tile (768 floats -> 4 shifted copies) + (1/T, vf)
    auto stage = [&](int buf, int tile) {
        const int base = tile * PPI;
        const unsigned gb = (unsigned)base * NK;
        const float v0 = __ldcs(&beta[gb + t]);
        const float v1 = __ldcs(&beta[gb + 256 + t]);
        #pragma unroll
        for (int s = 0; s < 4; ++s) {
            if (t >= s) sbc[buf][s][t - s] = v0;
            sbc[buf][s][256 + t - s] = v1;
        }
        if (t < 256) {
            const float v2 = __ldcs(&beta[gb + 512 + t]);
            #pragma unroll
            for (int s = 0; s < 4; ++s)
                if (512 + t - s < PPI * NK) sbc[buf][s][512 + t - s] = v2;
        }
        if (t < PPI) {
            sTV[buf][t].x = __frcp_rn(temperature[base + t]);
        } else if (t < 2 * PPI) {
            sTV[buf][t - PPI].y = view_factor[base + (t - PPI)];
        }
    };

    // prologue: static first tile + prefetch first dynamic tile id
    int cur = blockIdx.x;
    stage(0, cur);
    if (t == 0) sNext[0] = atomicAdd(&g_next, 1u);
    __syncthreads();

    int buf = 0, par = 0;
    while (cur < NTILES) {
        const int nxt = (int)sNext[par];
        if (t == 0) sNext[par ^ 1] = atomicAdd(&g_next, 1u);
        if (nxt < NTILES) stage(buf ^ 1, nxt);

        const unsigned ob = (unsigned)cur * (PPI * NCH) + (unsigned)t;

        // within-tile rolling s_obs ring
        float so[PF];
        #pragma unroll
        for (int p = 0; p < PF; ++p)
            so[p] = __ldcs(&s_obs[ob + (unsigned)(p * NCH)]);

        // smoothness from copy 0 (unshifted beta)
        {
            const float* b0 = &sbc[buf][0][oa];
            float d = b0[0] - 2.0f * b0[1] + b0[2];
            sss = fmaf(d, d, sss);
            const float* b1 = &sbc[buf][0][obs_];
            d = b1[0] - 2.0f * b1[1] + b1[2];
            sss = fmaf(d, d, sss);
            if (has_c) {
                const float* b2 = &sbc[buf][0][oc];
                d = b2[0] - 2.0f * b2[1] + b2[2];
                sss = fmaf(d, d, sss);
            }
        }

        const float* bbase = &sbc[buf][csel][coff];

        #pragma unroll
        for (int p = 0; p < PPI; ++p) {
            // consume FIRST, then refill the slot (ring-correct)
            const float so_cur = so[p & (PF - 1)];
            if (p + PF < PPI)
                so[p & (PF - 1)] =
                    __ldcs(&s_obs[ob + (unsigned)((p + PF) * NCH)]);

            // one aligned LDS.128 for the whole beta window
            const float4 bq = *reinterpret_cast<const float4*>(bbase + p * NK);
            float e = w0 * bq.x;
            e = fmaf(w1, bq.y, e);
            e = fmaf(w2, bq.z, e);
            e = fmaf(w3, bq.w, e);

            const float2 tv  = sTV[buf][p];
            const float  E   = exp2f(c2l * tv.x);
            const float  pl  = __fdividef(c1, E - 1.0f);
            const float  xa  = fmaf(tv.y, dsg, sg);
            const float  sm  = fmaf(e, pl - xa, xa);

            __stcs(&s_model[ob + (unsigned)(p * NCH)], sm);

            const float r = so_cur - sm;
            rs  = fmaf(r, r, rs);
            // relu(.01-e)+relu(e-.99) == max(|e-0.5|-0.49, 0)
            bvs += fmaxf(fabsf(e - 0.5f) - 0.49f, 0.0f);
        }

        __syncthreads();
        buf ^= 1;
        par ^= 1;
        cur  = nxt;
    }

    // ---- block reduction ----
    const unsigned m = 0xffffffffu;
    #pragma unroll
    for (int o = 16; o > 0; o >>= 1) {
        rs  += __shfl_down_sync(m, rs,  o);
        bvs += __shfl_down_sync(m, bvs, o);
        sss += __shfl_down_sync(m, sss, o);
    }
    if (lane == 0) { wred[0][wid] = rs; wred[1][wid] = bvs; wred[2][wid] = sss; }
    __syncthreads();

    if (t == 0) {
        double a = 0.0, b = 0.0, c = 0.0;
        #pragma unroll
        for (int i = 0; i < 8; ++i) {
            a += (double)wred[0][i];
            b += (double)wred[1][i];
            c += (double)wred[2][i];
        }
        atomicAdd(&g_res, a);
        atomicAdd(&g_bv,  b);
        atomicAdd(&g_ss,  c);
        __threadfence();
        const unsigned done = atomicAdd(&g_count, 1u);
        if (done == (unsigned)(GRID - 1)) {
            const double rr = atomicAdd(&g_res, 0.0);
            const double bb = atomicAdd(&g_bv,  0.0);
            const double cc = atomicAdd(&g_ss,  0.0);
            const double n  = (double)NPIX;
            if (write_total)
                out_total[0] = (float)(rr / n + 0.5 * cc / n + 10.0 * bb / n);
            // reset ALL persistent state for the next (graph-replayed) launch
            g_res = 0.0; g_bv = 0.0; g_ss = 0.0; g_count = 0u;
            g_next = (unsigned)GRID;
        }
    }
}

// ---------------- launch ----------------
extern "C" void kernel_launch(void* const* d_in, const int* in_sizes, int n_in,
                              void* d_out, int out_size)
{
    const float* s_obs       = (const float*)d_in[0];
    const float* temperature = (const float*)d_in[1];
    const float* beta        = (const float*)d_in[2];
    const float* view_factor = (const float*)d_in[3];
    const float* s_sky       = (const float*)d_in[4];
    const float* s_ground    = (const float*)d_in[5];
    const float* phi         = (const float*)d_in[6];
    // d_in[7] = d_beta (2nd-difference operator, applied analytically)
    const float* wn          = (const float*)d_in[8];

    float* out = (float*)d_out;
    const int off = out_size - NPIX * NCH;   // expected 1 (total scalar first)
    float* smodel = out + (off > 0 ? off : 0);

    fused_kernel<<<GRID, 256>>>(s_obs, temperature, beta, view_factor,
                                s_sky, s_ground, phi, wn,
                                smodel, out, off > 0 ? 1 : 0);
}

// round 16
// speedup vs baseline: 1.0285x; 1.0285x over previous
#include <cuda_runtime.h>
#include <math.h>

#define NPIX   262144
#define NCH    256
#define NK     24            // n_knots + degree + 1
#define ND     22            // second-difference rows
#define PPI    32            // pixels per tile
#define PF     4             // s_obs ring depth (power of 2, <= PPI)
#define NTILES (NPIX / PPI)  // 8192
#define GRID   888           // 148 SMs * 6 resident blocks

#define C1F    1.191042e-08f
#define C2L2EF (1.4387769f * 1.4426950408889634f)   // C2 * log2(e)

// ---------------- persistent device scratch (no allocations) ----------------
__device__ double   g_res;
__device__ double   g_ss;
__device__ double   g_bv;
__device__ unsigned g_count;

__global__ void __launch_bounds__(256, 6)
fused_kernel(const float* __restrict__ s_obs,
             const float* __restrict__ temperature,
             const float* __restrict__ beta,
             const float* __restrict__ view_factor,
             const float* __restrict__ s_sky,
             const float* __restrict__ s_ground,
             const float* __restrict__ phi,
             const float* __restrict__ wn,
             float* __restrict__ s_model,     // 4B aligned only (d_out+1)
             float* __restrict__ out_total,
             int write_total)
{
    // 4 shifted copies of the beta tile: copy s holds beta[k+s] at index k,
    // so window beta[k0..k0+3] is one aligned LDS.128 from copy (k0&3).
    __shared__ float  sbc[2][4][PPI * NK];   // 2 x 4 x 768 floats = 24.6 KB
    __shared__ float2 sTV[2][PPI];           // (1/T, vf) per pixel
    __shared__ float  wred[3][8];

    const int t    = threadIdx.x;        // t == channel
    const int wid  = t >> 5;
    const int lane = t & 31;

    // ---- per-channel constants (one-time; phi/wn tiny, L2-resident) ----
    const float* row = phi + t * NK;
    int k0 = 0;
    #pragma unroll
    for (int k = 0; k < NK; ++k) {
        if (row[k] != 0.0f) { k0 = k; break; }
    }
    if (k0 > NK - 4) k0 = NK - 4;
    const float w0 = row[k0],     w1 = row[k0 + 1];
    const float w2 = row[k0 + 2], w3 = row[k0 + 3];
    const float v   = wn[t];
    const float c1  = C1F * v * v * v;
    const float c2l = C2L2EF * v;        // exp(C2 v/T) == exp2(c2l/T)
    const float sg  = s_ground[t];
    const float dsg = s_sky[t] - sg;

    const int csel = k0 & 3;             // which shifted copy
    const int coff = k0 - csel;          // 16B-aligned float offset in that copy

    // smoothness: PPI*ND = 704 rows; thread handles t, t+256, t+512 (if <704)
    const int  ia = t,        oa   = (ia / ND) * NK + (ia % ND);
    const int  ib = t + 256,  obs_ = (ib / ND) * NK + (ib % ND);
    const int  ic = t + 512,  oc   = (ic / ND) * NK + (ic % ND);
    const bool has_c = ic < PPI * ND;    // t < 192

    float rs = 0.0f, bvs = 0.0f, sss = 0.0f;

    // stage beta tile (768 floats -> 4 shifted copies) + (1/T, vf)
    auto stage = [&](int buf, int tile) {
        const int base = tile * PPI;
        const unsigned gb = (unsigned)base * NK;
        const float v0 = __ldcs(&beta[gb + t]);
        const float v1 = __ldcs(&beta[gb + 256 + t]);
        #pragma unroll
        for (int s = 0; s < 4; ++s) {
            if (t >= s) sbc[buf][s][t - s] = v0;
            sbc[buf][s][256 + t - s] = v1;
        }
        if (t < 256) {
            const float v2 = __ldcs(&beta[gb + 512 + t]);
            #pragma unroll
            for (int s = 0; s < 4; ++s)
                if (512 + t - s < PPI * NK) sbc[buf][s][512 + t - s] = v2;
        }
        if (t < PPI) {
            sTV[buf][t].x = __frcp_rn(temperature[base + t]);
        } else if (t < 2 * PPI) {
            sTV[buf][t - PPI].y = view_factor[base + (t - PPI)];
        }
    };

    int tile = blockIdx.x;
    stage(0, tile);
    __syncthreads();

    int buf = 0;
    for (; tile < NTILES; tile += GRID) {
        const int nxt = tile + GRID;
        if (nxt < NTILES) stage(buf ^ 1, nxt);

        const unsigned ob = (unsigned)tile * (PPI * NCH) + (unsigned)t;

        // within-tile rolling s_obs ring
        float so[PF];
        #pragma unroll
        for (int p = 0; p < PF; ++p)
            so[p] = __ldcs(&s_obs[ob + (unsigned)(p * NCH)]);

        // smoothness from copy 0 (unshifted beta)
        {
            const float* b0 = &sbc[buf][0][oa];
            float d = b0[0] - 2.0f * b0[1] + b0[2];
            sss = fmaf(d, d, sss);
            const float* b1 = &sbc[buf][0][obs_];
            d = b1[0] - 2.0f * b1[1] + b1[2];
            sss = fmaf(d, d, sss);
            if (has_c) {
                const float* b2 = &sbc[buf][0][oc];
                d = b2[0] - 2.0f * b2[1] + b2[2];
                sss = fmaf(d, d, sss);
            }
        }

        const float* bbase = &sbc[buf][csel][coff];

        #pragma unroll
        for (int p = 0; p < PPI; ++p) {
            // consume FIRST, then refill the slot (ring-correct)
            const float so_cur = so[p & (PF - 1)];
            if (p + PF < PPI)
                so[p & (PF - 1)] =
                    __ldcs(&s_obs[ob + (unsigned)((p + PF) * NCH)]);

            // one aligned LDS.128 for the whole beta window
            const float4 bq = *reinterpret_cast<const float4*>(bbase + p * NK);
            float e = w0 * bq.x;
            e = fmaf(w1, bq.y, e);
            e = fmaf(w2, bq.z, e);
            e = fmaf(w3, bq.w, e);

            const float2 tv  = sTV[buf][p];
            const float  E   = exp2f(c2l * tv.x);
            const float  pl  = __fdividef(c1, E - 1.0f);
            const float  xa  = fmaf(tv.y, dsg, sg);
            const float  sm  = fmaf(e, pl - xa, xa);

            __stcs(&s_model[ob + (unsigned)(p * NCH)], sm);

            const float r = so_cur - sm;
            rs  = fmaf(r, r, rs);
            // relu(.01-e)+relu(e-.99) == max(|e-0.5|-0.49, 0)
            bvs += fmaxf(fabsf(e - 0.5f) - 0.49f, 0.0f);
        }

        __syncthreads();
        buf ^= 1;
    }

    // ---- block reduction ----
    const unsigned m = 0xffffffffu;
    #pragma unroll
    for (int o = 16; o > 0; o >>= 1) {
        rs  += __shfl_down_sync(m, rs,  o);
        bvs += __shfl_down_sync(m, bvs, o);
        sss += __shfl_down_sync(m, sss, o);
    }
    if (lane == 0) { wred[0][wid] = rs; wred[1][wid] = bvs; wred[2][wid] = sss; }
    __syncthreads();

    if (t == 0) {
        double a = 0.0, b = 0.0, c = 0.0;
        #pragma unroll
        for (int i = 0; i < 8; ++i) {
            a += (double)wred[0][i];
            b += (double)wred[1][i];
            c += (double)wred[2][i];
        }
        atomicAdd(&g_res, a);
        atomicAdd(&g_bv,  b);
        atomicAdd(&g_ss,  c);
        __threadfence();
        const unsigned done = atomicAdd(&g_count, 1u);
        if (done == (unsigned)(GRID - 1)) {
            const double rr = atomicAdd(&g_res, 0.0);
            const double bb = atomicAdd(&g_bv,  0.0);
            const double cc = atomicAdd(&g_ss,  0.0);
            const double n  = (double)NPIX;
            if (write_total)
                out_total[0] = (float)(rr / n + 0.5 * cc / n + 10.0 * bb / n);
            g_res = 0.0; g_bv = 0.0; g_ss = 0.0; g_count = 0u;
        }
    }
}

// ---------------- launch ----------------
extern "C" void kernel_launch(void* const* d_in, const int* in_sizes, int n_in,
                              void* d_out, int out_size)
{
    const float* s_obs       = (const float*)d_in[0];
    const float* temperature = (const float*)d_in[1];
    const float* beta        = (const float*)d_in[2];
    const float* view_factor = (const float*)d_in[3];
    const float* s_sky       = (const float*)d_in[4];
    const float* s_ground    = (const float*)d_in[5];
    const float* phi         = (const float*)d_in[6];
    // d_in[7] = d_beta (2nd-difference operator, applied analytically)
    const float* wn          = (const float*)d_in[8];

    float* out = (float*)d_out;
    const int off = out_size - NPIX * NCH;   // expected 1 (total scalar first)
    float* smodel = out + (off > 0 ? off : 0);

    fused_kernel<<<GRID, 256>>>(s_obs, temperature, beta, view_factor,
                                s_sky, s_ground, phi, wn,
                                smodel, out, off > 0 ? 1 : 0);
}